// round 15
// baseline (speedup 1.0000x reference)
#include <cuda_runtime.h>
#include <cstdint>

#define B_    8
#define V_    100000
#define FIN_  32
#define K_    4
#define FOUT_ 64
#define E_    800000
#define FH    128                       // floats per vertex per half (32f x 4b, j = f*4+bl)
#define HVF   ((size_t)V_ * FH)         // floats per Chebyshev order per half
#define SCAN_B 98                       // scan blocks (98*1024 >= V_)
#define ESMEM (8192 * 4 + 8 * 128 * 16) // ws 32KB + xst 16KB = 48KB -> 4 blocks/SM

// ---- scratch (static device globals; no allocation) ----
__device__ float d_x[8ull * HVF];       // 2 halves x {x0T, x1, x2, x3}
__device__ int   d_counts[V_];          // zero at load; re-zeroed by scanscatter each run
__device__ int   d_rowptr[V_ + 1];
__device__ int   d_cursor[V_];
__device__ int   d_ccol[E_];
__device__ float d_cval[E_];
__device__ int   d_agg[SCAN_B];

// barrier state for scanscatter (reset by hist_kernel every replay)
__device__ unsigned s_count;
__device__ volatile unsigned s_phase;

// ---------------- packed f32x2 helpers ----------------
__device__ __forceinline__ unsigned long long pack2(float a, float b) {
    unsigned long long r;
    asm("mov.b64 %0, {%1, %2};" : "=l"(r) : "f"(a), "f"(b));
    return r;
}
__device__ __forceinline__ unsigned long long fma2(unsigned long long x,
                                                   unsigned long long y,
                                                   unsigned long long c) {
    unsigned long long r;
    asm("fma.rn.f32x2 %0, %1, %2, %3;" : "=l"(r) : "l"(x), "l"(y), "l"(c));
    return r;
}
__device__ __forceinline__ void unpack2(unsigned long long v, float& lo, float& hi) {
    asm("mov.b64 {%0, %1}, %2;" : "=f"(lo), "=f"(hi) : "l"(v));
}

// ---------------- 1. hist (+ barrier-state reset) ----------------
__global__ void hist_kernel(const int* __restrict__ rows) {
    if (blockIdx.x == 0 && threadIdx.x == 0) {
        s_count = 0; *(unsigned*)&s_phase = 0;
    }
    int e = blockIdx.x * blockDim.x + threadIdx.x;
    if (e < E_) atomicAdd(&d_counts[rows[e]], 1);
}

// ---------------- 2. scan (lookback) + grid barrier + scatter ----------------
__device__ __forceinline__ int block_exscan(int v, int* total) {
    const int lane = threadIdx.x & 31;
    const int wid = threadIdx.x >> 5;
    int inc = v;
    #pragma unroll
    for (int o = 1; o < 32; o <<= 1) {
        int n = __shfl_up_sync(0xffffffffu, inc, o);
        if (lane >= o) inc += n;
    }
    __shared__ int wsum[32];
    if (lane == 31) wsum[wid] = inc;
    __syncthreads();
    if (wid == 0) {
        int s = wsum[lane];
        #pragma unroll
        for (int o = 1; o < 32; o <<= 1) {
            int n = __shfl_up_sync(0xffffffffu, s, o);
            if (lane >= o) s += n;
        }
        wsum[lane] = s;
    }
    __syncthreads();
    int excl = inc - v + (wid ? wsum[wid - 1] : 0);
    *total = wsum[31];
    return excl;
}

__global__ __launch_bounds__(1024) void scanscatter_kernel(const int* __restrict__ rows,
                                                           const int* __restrict__ cols,
                                                           const float* __restrict__ vals) {
    const int gtid = blockIdx.x * 1024 + threadIdx.x;
    int c = (gtid < V_) ? d_counts[gtid] : 0;
    int total;
    int excl = block_exscan(c, &total);
    __shared__ int s_off;
    if (threadIdx.x == 0) {
        s_off = 0;
        __threadfence();
        atomicExch(&d_agg[blockIdx.x], total + 1);
    }
    __syncthreads();
    if ((int)threadIdx.x < (int)blockIdx.x) {
        int v;
        do { v = atomicAdd(&d_agg[threadIdx.x], 0); } while (v == 0);
        atomicAdd(&s_off, v - 1);
    }
    __syncthreads();
    const int off = s_off;
    if (gtid < V_) {
        int r = excl + off;
        d_rowptr[gtid] = r;
        d_cursor[gtid] = r;
    }
    if (gtid == 0) d_rowptr[V_] = E_;

    // grid barrier: rowptr/cursor visible everywhere before scatter
    __threadfence();
    __syncthreads();
    if (threadIdx.x == 0) {
        unsigned t = atomicAdd(&s_count, 1);
        if (t == SCAN_B - 1) {
            s_count = 0;
            __threadfence();
            *(unsigned*)&s_phase = 1;
        } else {
            while (s_phase < 1) { }
            __threadfence();
        }
    }
    __syncthreads();

    const int stride = SCAN_B * 1024;
    for (int i = gtid; i < V_; i += stride) d_counts[i] = 0;
    if (gtid < SCAN_B) d_agg[gtid] = 0;
    for (int e = gtid; e < E_; e += stride) {
        int r = rows[e];
        int p = atomicAdd(&d_cursor[r], 1);
        d_ccol[p] = cols[e];
        d_cval[p] = vals[e];
    }
}

// ---------------- 3. SpMM pass 1 + transpose (per batch-half) ----------------
__global__ __launch_bounds__(256) void spmm1t_kernel(const float* __restrict__ in, int h,
                                                     float* __restrict__ x0T,
                                                     float* __restrict__ x1g) {
    __shared__ float st[8][336];
    const int wrp = threadIdx.x >> 5;
    const int lane = threadIdx.x & 31;
    const int v = blockIdx.x * 8 + wrp;
    const int bl = lane >> 3;
    const int f0 = (lane & 7) * 4;
    const float* base = in + ((size_t)(h * 4 + bl) * V_) * FIN_ + f0;

    const int s = __ldg(&d_rowptr[v]);
    const int e = __ldg(&d_rowptr[v + 1]);

    float4 aA = make_float4(0.f, 0.f, 0.f, 0.f);
    float4 aB = make_float4(0.f, 0.f, 0.f, 0.f);
    int i = s;
    for (; i + 1 < e; i += 2) {
        int   c0 = __ldg(&d_ccol[i]);
        int   c1 = __ldg(&d_ccol[i + 1]);
        float w0 = __ldg(&d_cval[i]);
        float w1 = __ldg(&d_cval[i + 1]);
        float4 u = __ldg(reinterpret_cast<const float4*>(base + (size_t)c0 * FIN_));
        float4 q = __ldg(reinterpret_cast<const float4*>(base + (size_t)c1 * FIN_));
        aA.x = fmaf(w0, u.x, aA.x); aA.y = fmaf(w0, u.y, aA.y);
        aA.z = fmaf(w0, u.z, aA.z); aA.w = fmaf(w0, u.w, aA.w);
        aB.x = fmaf(w1, q.x, aB.x); aB.y = fmaf(w1, q.y, aB.y);
        aB.z = fmaf(w1, q.z, aB.z); aB.w = fmaf(w1, q.w, aB.w);
    }
    if (i < e) {
        int   c0 = __ldg(&d_ccol[i]);
        float w0 = __ldg(&d_cval[i]);
        float4 u = __ldg(reinterpret_cast<const float4*>(base + (size_t)c0 * FIN_));
        aA.x = fmaf(w0, u.x, aA.x); aA.y = fmaf(w0, u.y, aA.y);
        aA.z = fmaf(w0, u.z, aA.z); aA.w = fmaf(w0, u.w, aA.w);
    }
    aA.x += aB.x; aA.y += aB.y; aA.z += aB.z; aA.w += aB.w;

    float4 o0 = __ldg(reinterpret_cast<const float4*>(base + (size_t)v * FIN_));

    float* s1 = st[wrp];
    float* s0 = st[wrp] + 168;
    s1[(f0 + 0) * 5 + bl] = aA.x; s1[(f0 + 1) * 5 + bl] = aA.y;
    s1[(f0 + 2) * 5 + bl] = aA.z; s1[(f0 + 3) * 5 + bl] = aA.w;
    s0[(f0 + 0) * 5 + bl] = o0.x; s0[(f0 + 1) * 5 + bl] = o0.y;
    s0[(f0 + 2) * 5 + bl] = o0.z; s0[(f0 + 3) * 5 + bl] = o0.w;
    __syncwarp();

    float4 r1, r0;
    r1.x = s1[5 * lane + 0]; r1.y = s1[5 * lane + 1];
    r1.z = s1[5 * lane + 2]; r1.w = s1[5 * lane + 3];
    r0.x = s0[5 * lane + 0]; r0.y = s0[5 * lane + 1];
    r0.z = s0[5 * lane + 2]; r0.w = s0[5 * lane + 3];

    *reinterpret_cast<float4*>(&x1g[(size_t)v * FH + lane * 4]) = r1;
    *reinterpret_cast<float4*>(&x0T[(size_t)v * FH + lane * 4]) = r0;
}

// ---------------- 4. SpMM passes 2/3 (interleaved layout): y = 2*(L x) - z ----------
__global__ __launch_bounds__(256) void spmm2_kernel(const float* __restrict__ x,
                                                    const float* __restrict__ z,
                                                    float* __restrict__ y) {
    const int wrp = threadIdx.x >> 5;
    const int lane = threadIdx.x & 31;
    const int v = blockIdx.x * 8 + wrp;
    const int p = lane * 4;
    const int s = __ldg(&d_rowptr[v]);
    const int e = __ldg(&d_rowptr[v + 1]);

    float4 a0 = make_float4(0.f, 0.f, 0.f, 0.f);
    float4 a1 = make_float4(0.f, 0.f, 0.f, 0.f);
    int i = s;
    for (; i + 1 < e; i += 2) {
        int   c0 = __ldg(&d_ccol[i]);
        int   c1 = __ldg(&d_ccol[i + 1]);
        float w0 = __ldg(&d_cval[i]);
        float w1 = __ldg(&d_cval[i + 1]);
        float4 u = __ldg(reinterpret_cast<const float4*>(&x[(size_t)c0 * FH + p]));
        float4 q = __ldg(reinterpret_cast<const float4*>(&x[(size_t)c1 * FH + p]));
        a0.x = fmaf(w0, u.x, a0.x); a0.y = fmaf(w0, u.y, a0.y);
        a0.z = fmaf(w0, u.z, a0.z); a0.w = fmaf(w0, u.w, a0.w);
        a1.x = fmaf(w1, q.x, a1.x); a1.y = fmaf(w1, q.y, a1.y);
        a1.z = fmaf(w1, q.z, a1.z); a1.w = fmaf(w1, q.w, a1.w);
    }
    if (i < e) {
        int   c0 = __ldg(&d_ccol[i]);
        float w0 = __ldg(&d_cval[i]);
        float4 u = __ldg(reinterpret_cast<const float4*>(&x[(size_t)c0 * FH + p]));
        a0.x = fmaf(w0, u.x, a0.x); a0.y = fmaf(w0, u.y, a0.y);
        a0.z = fmaf(w0, u.z, a0.z); a0.w = fmaf(w0, u.w, a0.w);
    }
    float4 zv = __ldg(reinterpret_cast<const float4*>(&z[(size_t)v * FH + p]));
    float4 r;
    r.x = 2.f * (a0.x + a1.x) - zv.x;
    r.y = 2.f * (a0.y + a1.y) - zv.y;
    r.z = 2.f * (a0.z + a1.z) - zv.z;
    r.w = 2.f * (a0.w + a1.w) - zv.w;
    *reinterpret_cast<float4*>(&y[(size_t)v * FH + p]) = r;
}

// ---------------- 5. einsum: warp owns 4 vertices; k-streamed smem staging ----------
__global__ __launch_bounds__(256) void einsum_kernel(const float* __restrict__ w,
                                                     const float* __restrict__ bias,
                                                     float* __restrict__ out, int h,
                                                     const float* __restrict__ xb4) {
    extern __shared__ __align__(16) float sm[];
    float*  ws  = sm;                                   // 8192 floats (32KB)
    float4* xst = reinterpret_cast<float4*>(sm + 8192); // 8 warps * 128 float4 (16KB)

    const int t = threadIdx.x;
    #pragma unroll
    for (int i = 0; i < 32; i++) ws[i * 256 + t] = w[i * 256 + t];
    __syncthreads();

    const int wrp = t >> 5;
    const int lane = t & 31;
    const int v0 = blockIdx.x * 32 + wrp * 4;           // 3125 blocks * 32 v = V_
    float4* xw = xst + wrp * 128;                       // this warp's slice: [j][q]

    const float bo0 = __ldg(&bias[lane]);
    const float bo1 = __ldg(&bias[lane + 32]);

    unsigned long long a[4][2][2];                      // [vertex j][o-slot][batch pair]
    #pragma unroll
    for (int j = 0; j < 4; j++)
        #pragma unroll
        for (int s2 = 0; s2 < 2; s2++) { a[j][s2][0] = 0ull; a[j][s2][1] = 0ull; }

    #pragma unroll
    for (int k = 0; k < K_; k++) {
        // stage order k: 4 vertices x 32 float4
        #pragma unroll
        for (int i = 0; i < 4; i++) {
            int idx = i * 32 + lane;                    // 0..127, j = idx>>5, q = idx&31
            xw[idx] = __ldg(reinterpret_cast<const float4*>(
                xb4 + (size_t)k * HVF + (size_t)(v0 + (idx >> 5)) * FH + (idx & 31) * 4));
        }
        __syncwarp();

        #pragma unroll 4
        for (int f = 0; f < FIN_; f++) {
            float w0 = ws[f * 256 + k * 64 + lane];
            float w1 = ws[f * 256 + k * 64 + 32 + lane];
            unsigned long long wp0 = pack2(w0, w0);
            unsigned long long wp1 = pack2(w1, w1);
            #pragma unroll
            for (int j = 0; j < 4; j++) {
                ulonglong2 xv = *reinterpret_cast<const ulonglong2*>(
                    &xw[j * 32 + f]);                   // broadcast LDS.128
                a[j][0][0] = fma2(xv.x, wp0, a[j][0][0]);
                a[j][0][1] = fma2(xv.y, wp0, a[j][0][1]);
                a[j][1][0] = fma2(xv.x, wp1, a[j][1][0]);
                a[j][1][1] = fma2(xv.y, wp1, a[j][1][1]);
            }
        }
        __syncwarp();                                   // done reading before restage
    }

    #pragma unroll
    for (int j = 0; j < 4; j++) {
        const int v = v0 + j;
        #pragma unroll
        for (int s2 = 0; s2 < 2; s2++) {
            float b0, b1, b2, b3;
            unpack2(a[j][s2][0], b0, b1);
            unpack2(a[j][s2][1], b2, b3);
            const int o = lane + s2 * 32;
            const float bb = s2 ? bo1 : bo0;
            out[((size_t)(h * 4 + 0) * V_ + v) * FOUT_ + o] = b0 + bb;
            out[((size_t)(h * 4 + 1) * V_ + v) * FOUT_ + o] = b1 + bb;
            out[((size_t)(h * 4 + 2) * V_ + v) * FOUT_ + o] = b2 + bb;
            out[((size_t)(h * 4 + 3) * V_ + v) * FOUT_ + o] = b3 + bb;
        }
    }
}

// ---------------- launch ----------------
extern "C" void kernel_launch(void* const* d_in, const int* in_sizes, int n_in,
                              void* d_out, int out_size) {
    const float* inputs = (const float*)d_in[0];
    const int*   rows   = (const int*)d_in[1];
    const int*   cols   = (const int*)d_in[2];
    const float* vals   = (const float*)d_in[3];
    const float* weight = (const float*)d_in[4];
    const float* bias   = (const float*)d_in[5];
    float* out = (float*)d_out;

    float* xbase;
    cudaGetSymbolAddress((void**)&xbase, d_x);

    // one-time config (first call is the uncaptured correctness run)
    static cudaStream_t s2 = nullptr;
    static cudaEvent_t evS = nullptr, evJ = nullptr;
    if (s2 == nullptr) {
        cudaFuncSetAttribute(einsum_kernel,
                             cudaFuncAttributeMaxDynamicSharedMemorySize, ESMEM);
        cudaStreamCreateWithFlags(&s2, cudaStreamNonBlocking);
        cudaEventCreateWithFlags(&evS, cudaEventDisableTiming);
        cudaEventCreateWithFlags(&evJ, cudaEventDisableTiming);
    }

    float* x0T0 = xbase;
    float* x10  = x0T0 + HVF;
    float* x20  = x0T0 + 2 * HVF;
    float* x30  = x0T0 + 3 * HVF;
    float* x0T1 = xbase + 4 * HVF;
    float* x11  = x0T1 + HVF;
    float* x21  = x0T1 + 2 * HVF;
    float* x31  = x0T1 + 3 * HVF;

    // stream0: CSR + full h0 spmm chain
    hist_kernel<<<(E_ + 255) / 256, 256>>>(rows);
    scanscatter_kernel<<<SCAN_B, 1024>>>(rows, cols, vals);
    spmm1t_kernel<<<V_ / 8, 256>>>(inputs, 0, x0T0, x10);
    spmm2_kernel<<<V_ / 8, 256>>>(x10, x0T0, x20);
    spmm2_kernel<<<V_ / 8, 256>>>(x20, x10, x30);

    // skewed fork: h1's spmm chain starts only after h0's spmm chain is done,
    // so it co-runs with h0's einsum (complementary DRAM-vs-FMA profiles)
    cudaEventRecord(evS, 0);
    cudaStreamWaitEvent(s2, evS, 0);

    einsum_kernel<<<V_ / 32, 256, ESMEM>>>(weight, bias, out, 0, x0T0);   // stream0

    spmm1t_kernel<<<V_ / 8, 256, 0, s2>>>(inputs, 1, x0T1, x11);          // s2
    spmm2_kernel<<<V_ / 8, 256, 0, s2>>>(x11, x0T1, x21);                 // s2
    spmm2_kernel<<<V_ / 8, 256, 0, s2>>>(x21, x11, x31);                  // s2
    einsum_kernel<<<V_ / 32, 256, ESMEM, s2>>>(weight, bias, out, 1, x0T1); // s2

    // join: default stream waits for chain h=1
    cudaEventRecord(evJ, s2);
    cudaStreamWaitEvent((cudaStream_t)0, evJ, 0);
}

// round 16
// speedup vs baseline: 1.0660x; 1.0660x over previous
#include <cuda_runtime.h>
#include <cstdint>

#define B_    8
#define V_    100000
#define FIN_  32
#define K_    4
#define FOUT_ 64
#define E_    800000
#define FH    128                       // floats per vertex per half (32f x 4b, j = f*4+bl)
#define HVF   ((size_t)V_ * FH)         // floats per Chebyshev order per half
#define SCAN_B 98                       // scan blocks (98*1024 >= V_)
#define ESMEM (8192 * 4 + 2 * 8 * 128 * 16) // ws 32KB + 2x16KB xst = 64KB -> 3 blocks/SM

// ---- scratch (static device globals; no allocation) ----
__device__ float d_x[8ull * HVF];       // 2 halves x {x0T, x1, x2, x3}
__device__ int   d_counts[V_];          // zero at load; re-zeroed by scanscatter each run
__device__ int   d_rowptr[V_ + 1];
__device__ int   d_cursor[V_];
__device__ int   d_ccol[E_];
__device__ float d_cval[E_];
__device__ int   d_agg[SCAN_B];

// barrier state for scanscatter (reset by hist_kernel every replay)
__device__ unsigned s_count;
__device__ volatile unsigned s_phase;

// ---------------- packed f32x2 helpers ----------------
__device__ __forceinline__ unsigned long long pack2(float a, float b) {
    unsigned long long r;
    asm("mov.b64 %0, {%1, %2};" : "=l"(r) : "f"(a), "f"(b));
    return r;
}
__device__ __forceinline__ unsigned long long fma2(unsigned long long x,
                                                   unsigned long long y,
                                                   unsigned long long c) {
    unsigned long long r;
    asm("fma.rn.f32x2 %0, %1, %2, %3;" : "=l"(r) : "l"(x), "l"(y), "l"(c));
    return r;
}
__device__ __forceinline__ void unpack2(unsigned long long v, float& lo, float& hi) {
    asm("mov.b64 {%0, %1}, %2;" : "=f"(lo), "=f"(hi) : "l"(v));
}

// cp.async helpers (LDGSTS — register-free staging)
__device__ __forceinline__ void cp16(void* dst, const void* src) {
    uint32_t d = (uint32_t)__cvta_generic_to_shared(dst);
    asm volatile("cp.async.ca.shared.global [%0], [%1], 16;" :: "r"(d), "l"(src));
}
__device__ __forceinline__ void cp_commit() {
    asm volatile("cp.async.commit_group;" ::: "memory");
}
template <int N>
__device__ __forceinline__ void cp_wait() {
    asm volatile("cp.async.wait_group %0;" :: "n"(N) : "memory");
}

// ---------------- 1. hist (+ barrier-state reset) ----------------
__global__ void hist_kernel(const int* __restrict__ rows) {
    if (blockIdx.x == 0 && threadIdx.x == 0) {
        s_count = 0; *(unsigned*)&s_phase = 0;
    }
    int e = blockIdx.x * blockDim.x + threadIdx.x;
    if (e < E_) atomicAdd(&d_counts[rows[e]], 1);
}

// ---------------- 2. scan (lookback) + grid barrier + scatter ----------------
__device__ __forceinline__ int block_exscan(int v, int* total) {
    const int lane = threadIdx.x & 31;
    const int wid = threadIdx.x >> 5;
    int inc = v;
    #pragma unroll
    for (int o = 1; o < 32; o <<= 1) {
        int n = __shfl_up_sync(0xffffffffu, inc, o);
        if (lane >= o) inc += n;
    }
    __shared__ int wsum[32];
    if (lane == 31) wsum[wid] = inc;
    __syncthreads();
    if (wid == 0) {
        int s = wsum[lane];
        #pragma unroll
        for (int o = 1; o < 32; o <<= 1) {
            int n = __shfl_up_sync(0xffffffffu, s, o);
            if (lane >= o) s += n;
        }
        wsum[lane] = s;
    }
    __syncthreads();
    int excl = inc - v + (wid ? wsum[wid - 1] : 0);
    *total = wsum[31];
    return excl;
}

__global__ __launch_bounds__(1024) void scanscatter_kernel(const int* __restrict__ rows,
                                                           const int* __restrict__ cols,
                                                           const float* __restrict__ vals) {
    const int gtid = blockIdx.x * 1024 + threadIdx.x;
    int c = (gtid < V_) ? d_counts[gtid] : 0;
    int total;
    int excl = block_exscan(c, &total);
    __shared__ int s_off;
    if (threadIdx.x == 0) {
        s_off = 0;
        __threadfence();
        atomicExch(&d_agg[blockIdx.x], total + 1);
    }
    __syncthreads();
    if ((int)threadIdx.x < (int)blockIdx.x) {
        int v;
        do { v = atomicAdd(&d_agg[threadIdx.x], 0); } while (v == 0);
        atomicAdd(&s_off, v - 1);
    }
    __syncthreads();
    const int off = s_off;
    if (gtid < V_) {
        int r = excl + off;
        d_rowptr[gtid] = r;
        d_cursor[gtid] = r;
    }
    if (gtid == 0) d_rowptr[V_] = E_;

    // grid barrier: rowptr/cursor visible everywhere before scatter
    __threadfence();
    __syncthreads();
    if (threadIdx.x == 0) {
        unsigned t = atomicAdd(&s_count, 1);
        if (t == SCAN_B - 1) {
            s_count = 0;
            __threadfence();
            *(unsigned*)&s_phase = 1;
        } else {
            while (s_phase < 1) { }
            __threadfence();
        }
    }
    __syncthreads();

    const int stride = SCAN_B * 1024;
    for (int i = gtid; i < V_; i += stride) d_counts[i] = 0;
    if (gtid < SCAN_B) d_agg[gtid] = 0;
    for (int e = gtid; e < E_; e += stride) {
        int r = rows[e];
        int p = atomicAdd(&d_cursor[r], 1);
        d_ccol[p] = cols[e];
        d_cval[p] = vals[e];
    }
}

// ---------------- 3. SpMM pass 1 + transpose (per batch-half) ----------------
__global__ __launch_bounds__(256) void spmm1t_kernel(const float* __restrict__ in, int h,
                                                     float* __restrict__ x0T,
                                                     float* __restrict__ x1g) {
    __shared__ float st[8][336];
    const int wrp = threadIdx.x >> 5;
    const int lane = threadIdx.x & 31;
    const int v = blockIdx.x * 8 + wrp;
    const int bl = lane >> 3;
    const int f0 = (lane & 7) * 4;
    const float* base = in + ((size_t)(h * 4 + bl) * V_) * FIN_ + f0;

    const int s = __ldg(&d_rowptr[v]);
    const int e = __ldg(&d_rowptr[v + 1]);

    float4 aA = make_float4(0.f, 0.f, 0.f, 0.f);
    float4 aB = make_float4(0.f, 0.f, 0.f, 0.f);
    int i = s;
    for (; i + 1 < e; i += 2) {
        int   c0 = __ldg(&d_ccol[i]);
        int   c1 = __ldg(&d_ccol[i + 1]);
        float w0 = __ldg(&d_cval[i]);
        float w1 = __ldg(&d_cval[i + 1]);
        float4 u = __ldg(reinterpret_cast<const float4*>(base + (size_t)c0 * FIN_));
        float4 q = __ldg(reinterpret_cast<const float4*>(base + (size_t)c1 * FIN_));
        aA.x = fmaf(w0, u.x, aA.x); aA.y = fmaf(w0, u.y, aA.y);
        aA.z = fmaf(w0, u.z, aA.z); aA.w = fmaf(w0, u.w, aA.w);
        aB.x = fmaf(w1, q.x, aB.x); aB.y = fmaf(w1, q.y, aB.y);
        aB.z = fmaf(w1, q.z, aB.z); aB.w = fmaf(w1, q.w, aB.w);
    }
    if (i < e) {
        int   c0 = __ldg(&d_ccol[i]);
        float w0 = __ldg(&d_cval[i]);
        float4 u = __ldg(reinterpret_cast<const float4*>(base + (size_t)c0 * FIN_));
        aA.x = fmaf(w0, u.x, aA.x); aA.y = fmaf(w0, u.y, aA.y);
        aA.z = fmaf(w0, u.z, aA.z); aA.w = fmaf(w0, u.w, aA.w);
    }
    aA.x += aB.x; aA.y += aB.y; aA.z += aB.z; aA.w += aB.w;

    float4 o0 = __ldg(reinterpret_cast<const float4*>(base + (size_t)v * FIN_));

    float* s1 = st[wrp];
    float* s0 = st[wrp] + 168;
    s1[(f0 + 0) * 5 + bl] = aA.x; s1[(f0 + 1) * 5 + bl] = aA.y;
    s1[(f0 + 2) * 5 + bl] = aA.z; s1[(f0 + 3) * 5 + bl] = aA.w;
    s0[(f0 + 0) * 5 + bl] = o0.x; s0[(f0 + 1) * 5 + bl] = o0.y;
    s0[(f0 + 2) * 5 + bl] = o0.z; s0[(f0 + 3) * 5 + bl] = o0.w;
    __syncwarp();

    float4 r1, r0;
    r1.x = s1[5 * lane + 0]; r1.y = s1[5 * lane + 1];
    r1.z = s1[5 * lane + 2]; r1.w = s1[5 * lane + 3];
    r0.x = s0[5 * lane + 0]; r0.y = s0[5 * lane + 1];
    r0.z = s0[5 * lane + 2]; r0.w = s0[5 * lane + 3];

    *reinterpret_cast<float4*>(&x1g[(size_t)v * FH + lane * 4]) = r1;
    *reinterpret_cast<float4*>(&x0T[(size_t)v * FH + lane * 4]) = r0;
}

// ---------------- 4. SpMM passes 2/3 (interleaved layout): y = 2*(L x) - z ----------
__global__ __launch_bounds__(256) void spmm2_kernel(const float* __restrict__ x,
                                                    const float* __restrict__ z,
                                                    float* __restrict__ y) {
    const int wrp = threadIdx.x >> 5;
    const int lane = threadIdx.x & 31;
    const int v = blockIdx.x * 8 + wrp;
    const int p = lane * 4;
    const int s = __ldg(&d_rowptr[v]);
    const int e = __ldg(&d_rowptr[v + 1]);

    float4 a0 = make_float4(0.f, 0.f, 0.f, 0.f);
    float4 a1 = make_float4(0.f, 0.f, 0.f, 0.f);
    int i = s;
    for (; i + 1 < e; i += 2) {
        int   c0 = __ldg(&d_ccol[i]);
        int   c1 = __ldg(&d_ccol[i + 1]);
        float w0 = __ldg(&d_cval[i]);
        float w1 = __ldg(&d_cval[i + 1]);
        float4 u = __ldg(reinterpret_cast<const float4*>(&x[(size_t)c0 * FH + p]));
        float4 q = __ldg(reinterpret_cast<const float4*>(&x[(size_t)c1 * FH + p]));
        a0.x = fmaf(w0, u.x, a0.x); a0.y = fmaf(w0, u.y, a0.y);
        a0.z = fmaf(w0, u.z, a0.z); a0.w = fmaf(w0, u.w, a0.w);
        a1.x = fmaf(w1, q.x, a1.x); a1.y = fmaf(w1, q.y, a1.y);
        a1.z = fmaf(w1, q.z, a1.z); a1.w = fmaf(w1, q.w, a1.w);
    }
    if (i < e) {
        int   c0 = __ldg(&d_ccol[i]);
        float w0 = __ldg(&d_cval[i]);
        float4 u = __ldg(reinterpret_cast<const float4*>(&x[(size_t)c0 * FH + p]));
        a0.x = fmaf(w0, u.x, a0.x); a0.y = fmaf(w0, u.y, a0.y);
        a0.z = fmaf(w0, u.z, a0.z); a0.w = fmaf(w0, u.w, a0.w);
    }
    float4 zv = __ldg(reinterpret_cast<const float4*>(&z[(size_t)v * FH + p]));
    float4 r;
    r.x = 2.f * (a0.x + a1.x) - zv.x;
    r.y = 2.f * (a0.y + a1.y) - zv.y;
    r.z = 2.f * (a0.z + a1.z) - zv.z;
    r.w = 2.f * (a0.w + a1.w) - zv.w;
    *reinterpret_cast<float4*>(&y[(size_t)v * FH + p]) = r;
}

// ---------------- 5. einsum: warp owns 4 vertices; cp.async double-buffered k staging --
// smem: ws 32KB + 2x16KB xst = 64KB -> 3 blocks/SM. Order k+1 prefetched via LDGSTS
// while order k computes; wait_group + __syncwarp at the buffer swap (warp-private).
__global__ __launch_bounds__(256) void einsum_kernel(const float* __restrict__ w,
                                                     const float* __restrict__ bias,
                                                     float* __restrict__ out, int h,
                                                     const float* __restrict__ xb4) {
    extern __shared__ __align__(16) float sm[];
    float*  ws  = sm;                                   // 8192 floats (32KB)
    float4* xst = reinterpret_cast<float4*>(sm + 8192); // 2 x (8 warps x 128 float4)

    const int t = threadIdx.x;
    #pragma unroll
    for (int i = 0; i < 32; i++) ws[i * 256 + t] = w[i * 256 + t];
    __syncthreads();

    const int wrp = t >> 5;
    const int lane = t & 31;
    const int v0 = blockIdx.x * 32 + wrp * 4;           // 3125 blocks * 32 v = V_
    float4* xbuf[2] = { xst + wrp * 128, xst + 1024 + wrp * 128 };

    const float bo0 = __ldg(&bias[lane]);
    const float bo1 = __ldg(&bias[lane + 32]);

    // prologue: stage k=0 into buffer 0
    #pragma unroll
    for (int i = 0; i < 4; i++) {
        int idx = i * 32 + lane;
        cp16(&xbuf[0][idx],
             xb4 + (size_t)(v0 + (idx >> 5)) * FH + (idx & 31) * 4);
    }
    cp_commit();

    unsigned long long a[4][2][2];                      // [vertex j][o-slot][batch pair]
    #pragma unroll
    for (int j = 0; j < 4; j++)
        #pragma unroll
        for (int s2 = 0; s2 < 2; s2++) { a[j][s2][0] = 0ull; a[j][s2][1] = 0ull; }

    #pragma unroll
    for (int k = 0; k < K_; k++) {
        float4* cur = xbuf[k & 1];
        if (k < K_ - 1) {
            float4* nxt = xbuf[(k + 1) & 1];
            #pragma unroll
            for (int i = 0; i < 4; i++) {
                int idx = i * 32 + lane;
                cp16(&nxt[idx],
                     xb4 + (size_t)(k + 1) * HVF +
                     (size_t)(v0 + (idx >> 5)) * FH + (idx & 31) * 4);
            }
            cp_commit();
            cp_wait<1>();       // cur's group done; nxt may still be in flight
        } else {
            cp_wait<0>();
        }
        __syncwarp();

        #pragma unroll 4
        for (int f = 0; f < FIN_; f++) {
            float w0 = ws[f * 256 + k * 64 + lane];
            float w1 = ws[f * 256 + k * 64 + 32 + lane];
            unsigned long long wp0 = pack2(w0, w0);
            unsigned long long wp1 = pack2(w1, w1);
            #pragma unroll
            for (int j = 0; j < 4; j++) {
                ulonglong2 xv = *reinterpret_cast<const ulonglong2*>(
                    &cur[j * 32 + f]);                  // broadcast LDS.128
                a[j][0][0] = fma2(xv.x, wp0, a[j][0][0]);
                a[j][0][1] = fma2(xv.y, wp0, a[j][0][1]);
                a[j][1][0] = fma2(xv.x, wp1, a[j][1][0]);
                a[j][1][1] = fma2(xv.y, wp1, a[j][1][1]);
            }
        }
        __syncwarp();           // all lanes done reading cur before it is re-staged
    }

    #pragma unroll
    for (int j = 0; j < 4; j++) {
        const int v = v0 + j;
        #pragma unroll
        for (int s2 = 0; s2 < 2; s2++) {
            float b0, b1, b2, b3;
            unpack2(a[j][s2][0], b0, b1);
            unpack2(a[j][s2][1], b2, b3);
            const int o = lane + s2 * 32;
            const float bb = s2 ? bo1 : bo0;
            out[((size_t)(h * 4 + 0) * V_ + v) * FOUT_ + o] = b0 + bb;
            out[((size_t)(h * 4 + 1) * V_ + v) * FOUT_ + o] = b1 + bb;
            out[((size_t)(h * 4 + 2) * V_ + v) * FOUT_ + o] = b2 + bb;
            out[((size_t)(h * 4 + 3) * V_ + v) * FOUT_ + o] = b3 + bb;
        }
    }
}

// ---------------- launch ----------------
extern "C" void kernel_launch(void* const* d_in, const int* in_sizes, int n_in,
                              void* d_out, int out_size) {
    const float* inputs = (const float*)d_in[0];
    const int*   rows   = (const int*)d_in[1];
    const int*   cols   = (const int*)d_in[2];
    const float* vals   = (const float*)d_in[3];
    const float* weight = (const float*)d_in[4];
    const float* bias   = (const float*)d_in[5];
    float* out = (float*)d_out;

    float* xbase;
    cudaGetSymbolAddress((void**)&xbase, d_x);

    // one-time config (first call is the uncaptured correctness run)
    static cudaStream_t s2 = nullptr;
    static cudaEvent_t evF = nullptr, evJ = nullptr;
    if (s2 == nullptr) {
        cudaFuncSetAttribute(einsum_kernel,
                             cudaFuncAttributeMaxDynamicSharedMemorySize, ESMEM);
        cudaStreamCreateWithFlags(&s2, cudaStreamNonBlocking);
        cudaEventCreateWithFlags(&evF, cudaEventDisableTiming);
        cudaEventCreateWithFlags(&evJ, cudaEventDisableTiming);
    }

    hist_kernel<<<(E_ + 255) / 256, 256>>>(rows);                   // default stream
    scanscatter_kernel<<<SCAN_B, 1024>>>(rows, cols, vals);         // default stream

    // lock-step fork (best measured scheduling): chain h=1 on s2
    cudaEventRecord(evF, 0);
    cudaStreamWaitEvent(s2, evF, 0);

    for (int h = 0; h < 2; h++) {
        cudaStream_t st = (h == 0) ? (cudaStream_t)0 : s2;
        float* x0T = xbase + (size_t)h * 4 * HVF;
        float* x1  = x0T + HVF;
        float* x2  = x0T + 2 * HVF;
        float* x3  = x0T + 3 * HVF;
        spmm1t_kernel<<<V_ / 8, 256, 0, st>>>(inputs, h, x0T, x1);
        spmm2_kernel<<<V_ / 8, 256, 0, st>>>(x1, x0T, x2);
        spmm2_kernel<<<V_ / 8, 256, 0, st>>>(x2, x1, x3);
        einsum_kernel<<<V_ / 32, 256, ESMEM, st>>>(weight, bias, out, h, x0T);
    }

    // join: default stream waits for chain h=1
    cudaEventRecord(evJ, s2);
    cudaStreamWaitEvent((cudaStream_t)0, evJ, 0);
}

// round 17
// speedup vs baseline: 1.0836x; 1.0165x over previous
#include <cuda_runtime.h>
#include <cuda_fp16.h>
#include <cstdint>

#define B_    8
#define V_    100000
#define FIN_  32
#define K_    4
#define FOUT_ 64
#define E_    800000
#define FH    128                       // floats per vertex per half (32f x 4b, j = f*4+bl)
#define HVF   ((size_t)V_ * FH)         // floats per Chebyshev order per half
#define SCAN_B 98                       // scan blocks (98*1024 >= V_)
#define ESMEM (8192 * 4 + 2 * 8 * 128 * 16) // ws 32KB + 2x16KB xst = 64KB -> 3 blocks/SM

// ---- scratch (static device globals; no allocation) ----
__device__ float  d_x[8ull * HVF];      // 2 halves x {x0T, x1, x2, x3} (f32, einsum source)
__device__ __half d_xh[4ull * HVF];     // 2 halves x {x1h, x2h} (fp16 gather copies)
__device__ int   d_counts[V_];          // zero at load; re-zeroed by scanscatter each run
__device__ int   d_rowptr[V_ + 1];
__device__ int   d_cursor[V_];
__device__ int   d_ccol[E_];
__device__ float d_cval[E_];
__device__ int   d_agg[SCAN_B];

// barrier state for scanscatter (reset by hist_kernel every replay)
__device__ unsigned s_count;
__device__ volatile unsigned s_phase;

// ---------------- packed f32x2 helpers ----------------
__device__ __forceinline__ unsigned long long pack2(float a, float b) {
    unsigned long long r;
    asm("mov.b64 %0, {%1, %2};" : "=l"(r) : "f"(a), "f"(b));
    return r;
}
__device__ __forceinline__ unsigned long long fma2(unsigned long long x,
                                                   unsigned long long y,
                                                   unsigned long long c) {
    unsigned long long r;
    asm("fma.rn.f32x2 %0, %1, %2, %3;" : "=l"(r) : "l"(x), "l"(y), "l"(c));
    return r;
}
__device__ __forceinline__ void unpack2(unsigned long long v, float& lo, float& hi) {
    asm("mov.b64 {%0, %1}, %2;" : "=f"(lo), "=f"(hi) : "l"(v));
}

// cp.async helpers (LDGSTS — register-free staging)
__device__ __forceinline__ void cp16(void* dst, const void* src) {
    uint32_t d = (uint32_t)__cvta_generic_to_shared(dst);
    asm volatile("cp.async.ca.shared.global [%0], [%1], 16;" :: "r"(d), "l"(src));
}
__device__ __forceinline__ void cp_commit() {
    asm volatile("cp.async.commit_group;" ::: "memory");
}
template <int N>
__device__ __forceinline__ void cp_wait() {
    asm volatile("cp.async.wait_group %0;" :: "n"(N) : "memory");
}

// ---------------- 1. hist (+ barrier-state reset) ----------------
__global__ void hist_kernel(const int* __restrict__ rows) {
    if (blockIdx.x == 0 && threadIdx.x == 0) {
        s_count = 0; *(unsigned*)&s_phase = 0;
    }
    int e = blockIdx.x * blockDim.x + threadIdx.x;
    if (e < E_) atomicAdd(&d_counts[rows[e]], 1);
}

// ---------------- 2. scan (lookback) + grid barrier + scatter ----------------
__device__ __forceinline__ int block_exscan(int v, int* total) {
    const int lane = threadIdx.x & 31;
    const int wid = threadIdx.x >> 5;
    int inc = v;
    #pragma unroll
    for (int o = 1; o < 32; o <<= 1) {
        int n = __shfl_up_sync(0xffffffffu, inc, o);
        if (lane >= o) inc += n;
    }
    __shared__ int wsum[32];
    if (lane == 31) wsum[wid] = inc;
    __syncthreads();
    if (wid == 0) {
        int s = wsum[lane];
        #pragma unroll
        for (int o = 1; o < 32; o <<= 1) {
            int n = __shfl_up_sync(0xffffffffu, s, o);
            if (lane >= o) s += n;
        }
        wsum[lane] = s;
    }
    __syncthreads();
    int excl = inc - v + (wid ? wsum[wid - 1] : 0);
    *total = wsum[31];
    return excl;
}

__global__ __launch_bounds__(1024) void scanscatter_kernel(const int* __restrict__ rows,
                                                           const int* __restrict__ cols,
                                                           const float* __restrict__ vals) {
    const int gtid = blockIdx.x * 1024 + threadIdx.x;
    int c = (gtid < V_) ? d_counts[gtid] : 0;
    int total;
    int excl = block_exscan(c, &total);
    __shared__ int s_off;
    if (threadIdx.x == 0) {
        s_off = 0;
        __threadfence();
        atomicExch(&d_agg[blockIdx.x], total + 1);
    }
    __syncthreads();
    if ((int)threadIdx.x < (int)blockIdx.x) {
        int v;
        do { v = atomicAdd(&d_agg[threadIdx.x], 0); } while (v == 0);
        atomicAdd(&s_off, v - 1);
    }
    __syncthreads();
    const int off = s_off;
    if (gtid < V_) {
        int r = excl + off;
        d_rowptr[gtid] = r;
        d_cursor[gtid] = r;
    }
    if (gtid == 0) d_rowptr[V_] = E_;

    // grid barrier: rowptr/cursor visible everywhere before scatter
    __threadfence();
    __syncthreads();
    if (threadIdx.x == 0) {
        unsigned t = atomicAdd(&s_count, 1);
        if (t == SCAN_B - 1) {
            s_count = 0;
            __threadfence();
            *(unsigned*)&s_phase = 1;
        } else {
            while (s_phase < 1) { }
            __threadfence();
        }
    }
    __syncthreads();

    const int stride = SCAN_B * 1024;
    for (int i = gtid; i < V_; i += stride) d_counts[i] = 0;
    if (gtid < SCAN_B) d_agg[gtid] = 0;
    for (int e = gtid; e < E_; e += stride) {
        int r = rows[e];
        int p = atomicAdd(&d_cursor[r], 1);
        d_ccol[p] = cols[e];
        d_cval[p] = vals[e];
    }
}

// ---------------- 3. SpMM pass 1 + transpose (per batch-half) ----------------
// Writes x1 (f32) + x1h (fp16 gather copy) + x0T (f32).
__global__ __launch_bounds__(256) void spmm1t_kernel(const float* __restrict__ in, int h,
                                                     float* __restrict__ x0T,
                                                     float* __restrict__ x1g,
                                                     __half* __restrict__ x1h) {
    __shared__ float st[8][336];
    const int wrp = threadIdx.x >> 5;
    const int lane = threadIdx.x & 31;
    const int v = blockIdx.x * 8 + wrp;
    const int bl = lane >> 3;
    const int f0 = (lane & 7) * 4;
    const float* base = in + ((size_t)(h * 4 + bl) * V_) * FIN_ + f0;

    const int s = __ldg(&d_rowptr[v]);
    const int e = __ldg(&d_rowptr[v + 1]);

    float4 aA = make_float4(0.f, 0.f, 0.f, 0.f);
    float4 aB = make_float4(0.f, 0.f, 0.f, 0.f);
    int i = s;
    for (; i + 1 < e; i += 2) {
        int   c0 = __ldg(&d_ccol[i]);
        int   c1 = __ldg(&d_ccol[i + 1]);
        float w0 = __ldg(&d_cval[i]);
        float w1 = __ldg(&d_cval[i + 1]);
        float4 u = __ldg(reinterpret_cast<const float4*>(base + (size_t)c0 * FIN_));
        float4 q = __ldg(reinterpret_cast<const float4*>(base + (size_t)c1 * FIN_));
        aA.x = fmaf(w0, u.x, aA.x); aA.y = fmaf(w0, u.y, aA.y);
        aA.z = fmaf(w0, u.z, aA.z); aA.w = fmaf(w0, u.w, aA.w);
        aB.x = fmaf(w1, q.x, aB.x); aB.y = fmaf(w1, q.y, aB.y);
        aB.z = fmaf(w1, q.z, aB.z); aB.w = fmaf(w1, q.w, aB.w);
    }
    if (i < e) {
        int   c0 = __ldg(&d_ccol[i]);
        float w0 = __ldg(&d_cval[i]);
        float4 u = __ldg(reinterpret_cast<const float4*>(base + (size_t)c0 * FIN_));
        aA.x = fmaf(w0, u.x, aA.x); aA.y = fmaf(w0, u.y, aA.y);
        aA.z = fmaf(w0, u.z, aA.z); aA.w = fmaf(w0, u.w, aA.w);
    }
    aA.x += aB.x; aA.y += aB.y; aA.z += aB.z; aA.w += aB.w;

    float4 o0 = __ldg(reinterpret_cast<const float4*>(base + (size_t)v * FIN_));

    float* s1 = st[wrp];
    float* s0 = st[wrp] + 168;
    s1[(f0 + 0) * 5 + bl] = aA.x; s1[(f0 + 1) * 5 + bl] = aA.y;
    s1[(f0 + 2) * 5 + bl] = aA.z; s1[(f0 + 3) * 5 + bl] = aA.w;
    s0[(f0 + 0) * 5 + bl] = o0.x; s0[(f0 + 1) * 5 + bl] = o0.y;
    s0[(f0 + 2) * 5 + bl] = o0.z; s0[(f0 + 3) * 5 + bl] = o0.w;
    __syncwarp();

    float4 r1, r0;
    r1.x = s1[5 * lane + 0]; r1.y = s1[5 * lane + 1];
    r1.z = s1[5 * lane + 2]; r1.w = s1[5 * lane + 3];
    r0.x = s0[5 * lane + 0]; r0.y = s0[5 * lane + 1];
    r0.z = s0[5 * lane + 2]; r0.w = s0[5 * lane + 3];

    *reinterpret_cast<float4*>(&x1g[(size_t)v * FH + lane * 4]) = r1;
    *reinterpret_cast<float4*>(&x0T[(size_t)v * FH + lane * 4]) = r0;

    // fp16 gather copy of x1
    __half2 h0 = __float22half2_rn(make_float2(r1.x, r1.y));
    __half2 h1 = __float22half2_rn(make_float2(r1.z, r1.w));
    uint2 u16;
    u16.x = *reinterpret_cast<const unsigned*>(&h0);
    u16.y = *reinterpret_cast<const unsigned*>(&h1);
    *reinterpret_cast<uint2*>(&x1h[(size_t)v * FH + lane * 4]) = u16;
}

// ---------------- 4. SpMM passes 2/3: y = 2*(L xh) - z, fp16 gather ----------------
__global__ __launch_bounds__(256) void spmm2h_kernel(const __half* __restrict__ xh,
                                                     const float* __restrict__ z,
                                                     float* __restrict__ y,
                                                     __half* __restrict__ yh) {
    const int wrp = threadIdx.x >> 5;
    const int lane = threadIdx.x & 31;
    const int v = blockIdx.x * 8 + wrp;
    const int p = lane * 4;
    const int s = __ldg(&d_rowptr[v]);
    const int e = __ldg(&d_rowptr[v + 1]);

    float4 a0 = make_float4(0.f, 0.f, 0.f, 0.f);
    float4 a1 = make_float4(0.f, 0.f, 0.f, 0.f);
    int i = s;
    for (; i + 1 < e; i += 2) {
        int   c0 = __ldg(&d_ccol[i]);
        int   c1 = __ldg(&d_ccol[i + 1]);
        float w0 = __ldg(&d_cval[i]);
        float w1 = __ldg(&d_cval[i + 1]);
        uint2 ra = __ldg(reinterpret_cast<const uint2*>(xh + (size_t)c0 * FH + p));
        uint2 rb = __ldg(reinterpret_cast<const uint2*>(xh + (size_t)c1 * FH + p));
        float2 a_lo = __half22float2(*reinterpret_cast<const __half2*>(&ra.x));
        float2 a_hi = __half22float2(*reinterpret_cast<const __half2*>(&ra.y));
        float2 b_lo = __half22float2(*reinterpret_cast<const __half2*>(&rb.x));
        float2 b_hi = __half22float2(*reinterpret_cast<const __half2*>(&rb.y));
        a0.x = fmaf(w0, a_lo.x, a0.x); a0.y = fmaf(w0, a_lo.y, a0.y);
        a0.z = fmaf(w0, a_hi.x, a0.z); a0.w = fmaf(w0, a_hi.y, a0.w);
        a1.x = fmaf(w1, b_lo.x, a1.x); a1.y = fmaf(w1, b_lo.y, a1.y);
        a1.z = fmaf(w1, b_hi.x, a1.z); a1.w = fmaf(w1, b_hi.y, a1.w);
    }
    if (i < e) {
        int   c0 = __ldg(&d_ccol[i]);
        float w0 = __ldg(&d_cval[i]);
        uint2 ra = __ldg(reinterpret_cast<const uint2*>(xh + (size_t)c0 * FH + p));
        float2 a_lo = __half22float2(*reinterpret_cast<const __half2*>(&ra.x));
        float2 a_hi = __half22float2(*reinterpret_cast<const __half2*>(&ra.y));
        a0.x = fmaf(w0, a_lo.x, a0.x); a0.y = fmaf(w0, a_lo.y, a0.y);
        a0.z = fmaf(w0, a_hi.x, a0.z); a0.w = fmaf(w0, a_hi.y, a0.w);
    }
    float4 zv = __ldg(reinterpret_cast<const float4*>(&z[(size_t)v * FH + p]));
    float4 r;
    r.x = 2.f * (a0.x + a1.x) - zv.x;
    r.y = 2.f * (a0.y + a1.y) - zv.y;
    r.z = 2.f * (a0.z + a1.z) - zv.z;
    r.w = 2.f * (a0.w + a1.w) - zv.w;
    *reinterpret_cast<float4*>(&y[(size_t)v * FH + p]) = r;

    if (yh != nullptr) {
        __half2 h0 = __float22half2_rn(make_float2(r.x, r.y));
        __half2 h1 = __float22half2_rn(make_float2(r.z, r.w));
        uint2 u16;
        u16.x = *reinterpret_cast<const unsigned*>(&h0);
        u16.y = *reinterpret_cast<const unsigned*>(&h1);
        *reinterpret_cast<uint2*>(&yh[(size_t)v * FH + p]) = u16;
    }
}

// ---------------- 5. einsum: warp owns 4 vertices; cp.async double-buffered k staging --
__global__ __launch_bounds__(256) void einsum_kernel(const float* __restrict__ w,
                                                     const float* __restrict__ bias,
                                                     float* __restrict__ out, int h,
                                                     const float* __restrict__ xb4) {
    extern __shared__ __align__(16) float sm[];
    float*  ws  = sm;                                   // 8192 floats (32KB)
    float4* xst = reinterpret_cast<float4*>(sm + 8192); // 2 x (8 warps x 128 float4)

    const int t = threadIdx.x;
    #pragma unroll
    for (int i = 0; i < 32; i++) ws[i * 256 + t] = w[i * 256 + t];
    __syncthreads();

    const int wrp = t >> 5;
    const int lane = t & 31;
    const int v0 = blockIdx.x * 32 + wrp * 4;           // 3125 blocks * 32 v = V_
    float4* xbuf[2] = { xst + wrp * 128, xst + 1024 + wrp * 128 };

    const float bo0 = __ldg(&bias[lane]);
    const float bo1 = __ldg(&bias[lane + 32]);

    // prologue: stage k=0 into buffer 0
    #pragma unroll
    for (int i = 0; i < 4; i++) {
        int idx = i * 32 + lane;
        cp16(&xbuf[0][idx],
             xb4 + (size_t)(v0 + (idx >> 5)) * FH + (idx & 31) * 4);
    }
    cp_commit();

    unsigned long long a[4][2][2];                      // [vertex j][o-slot][batch pair]
    #pragma unroll
    for (int j = 0; j < 4; j++)
        #pragma unroll
        for (int s2 = 0; s2 < 2; s2++) { a[j][s2][0] = 0ull; a[j][s2][1] = 0ull; }

    #pragma unroll
    for (int k = 0; k < K_; k++) {
        float4* cur = xbuf[k & 1];
        if (k < K_ - 1) {
            float4* nxt = xbuf[(k + 1) & 1];
            #pragma unroll
            for (int i = 0; i < 4; i++) {
                int idx = i * 32 + lane;
                cp16(&nxt[idx],
                     xb4 + (size_t)(k + 1) * HVF +
                     (size_t)(v0 + (idx >> 5)) * FH + (idx & 31) * 4);
            }
            cp_commit();
            cp_wait<1>();       // cur's group done; nxt may still be in flight
        } else {
            cp_wait<0>();
        }
        __syncwarp();

        #pragma unroll 4
        for (int f = 0; f < FIN_; f++) {
            float w0 = ws[f * 256 + k * 64 + lane];
            float w1 = ws[f * 256 + k * 64 + 32 + lane];
            unsigned long long wp0 = pack2(w0, w0);
            unsigned long long wp1 = pack2(w1, w1);
            #pragma unroll
            for (int j = 0; j < 4; j++) {
                ulonglong2 xv = *reinterpret_cast<const ulonglong2*>(
                    &cur[j * 32 + f]);                  // broadcast LDS.128
                a[j][0][0] = fma2(xv.x, wp0, a[j][0][0]);
                a[j][0][1] = fma2(xv.y, wp0, a[j][0][1]);
                a[j][1][0] = fma2(xv.x, wp1, a[j][1][0]);
                a[j][1][1] = fma2(xv.y, wp1, a[j][1][1]);
            }
        }
        __syncwarp();           // all lanes done reading cur before it is re-staged
    }

    #pragma unroll
    for (int j = 0; j < 4; j++) {
        const int v = v0 + j;
        #pragma unroll
        for (int s2 = 0; s2 < 2; s2++) {
            float b0, b1, b2, b3;
            unpack2(a[j][s2][0], b0, b1);
            unpack2(a[j][s2][1], b2, b3);
            const int o = lane + s2 * 32;
            const float bb = s2 ? bo1 : bo0;
            out[((size_t)(h * 4 + 0) * V_ + v) * FOUT_ + o] = b0 + bb;
            out[((size_t)(h * 4 + 1) * V_ + v) * FOUT_ + o] = b1 + bb;
            out[((size_t)(h * 4 + 2) * V_ + v) * FOUT_ + o] = b2 + bb;
            out[((size_t)(h * 4 + 3) * V_ + v) * FOUT_ + o] = b3 + bb;
        }
    }
}

// ---------------- launch ----------------
extern "C" void kernel_launch(void* const* d_in, const int* in_sizes, int n_in,
                              void* d_out, int out_size) {
    const float* inputs = (const float*)d_in[0];
    const int*   rows   = (const int*)d_in[1];
    const int*   cols   = (const int*)d_in[2];
    const float* vals   = (const float*)d_in[3];
    const float* weight = (const float*)d_in[4];
    const float* bias   = (const float*)d_in[5];
    float* out = (float*)d_out;

    float* xbase;
    cudaGetSymbolAddress((void**)&xbase, d_x);
    __half* xhbase;
    cudaGetSymbolAddress((void**)&xhbase, d_xh);

    // one-time config (first call is the uncaptured correctness run)
    static cudaStream_t s2 = nullptr;
    static cudaEvent_t evF = nullptr, evJ = nullptr;
    if (s2 == nullptr) {
        cudaFuncSetAttribute(einsum_kernel,
                             cudaFuncAttributeMaxDynamicSharedMemorySize, ESMEM);
        cudaStreamCreateWithFlags(&s2, cudaStreamNonBlocking);
        cudaEventCreateWithFlags(&evF, cudaEventDisableTiming);
        cudaEventCreateWithFlags(&evJ, cudaEventDisableTiming);
    }

    hist_kernel<<<(E_ + 255) / 256, 256>>>(rows);                   // default stream
    scanscatter_kernel<<<SCAN_B, 1024>>>(rows, cols, vals);         // default stream

    // lock-step fork (best measured scheduling): chain h=1 on s2
    cudaEventRecord(evF, 0);
    cudaStreamWaitEvent(s2, evF, 0);

    for (int h = 0; h < 2; h++) {
        cudaStream_t st = (h == 0) ? (cudaStream_t)0 : s2;
        float* x0T = xbase + (size_t)h * 4 * HVF;
        float* x1  = x0T + HVF;
        float* x2  = x0T + 2 * HVF;
        float* x3  = x0T + 3 * HVF;
        __half* x1h = xhbase + (size_t)h * 2 * HVF;
        __half* x2h = x1h + HVF;
        spmm1t_kernel<<<V_ / 8, 256, 0, st>>>(inputs, h, x0T, x1, x1h);
        spmm2h_kernel<<<V_ / 8, 256, 0, st>>>(x1h, x0T, x2, x2h);
        spmm2h_kernel<<<V_ / 8, 256, 0, st>>>(x2h, x1, x3, nullptr);
        einsum_kernel<<<V_ / 32, 256, ESMEM, st>>>(weight, bias, out, h, x0T);
    }

    // join: default stream waits for chain h=1
    cudaEventRecord(evJ, s2);
    cudaStreamWaitEvent((cudaStream_t)0, evJ, 0);
}